// round 2
// baseline (speedup 1.0000x reference)
#include <cuda_runtime.h>
#include <cuda_bf16.h>
#include <math.h>

// Problem constants
#define BB    4
#define NN    4096
#define DD    256
#define MM    (BB * NN)        // 16384 flattened rows
#define MAXNZ 128              // Poisson(32) row nnz; P(>128) ~ 0

// Scratch (static __device__ — no allocations allowed)
static __device__ float g_norm[MM];
static __device__ int   g_nnz[MM];
static __device__ int   g_cidx[MM * MAXNZ];
static __device__ float g_cval[MM * MAXNZ];
static __device__ float g_h[MM * DD];      // norm-scaled x@theta
static __device__ float g_het[MM * DD];    // x@W_h
static __device__ float g_gate[MM * DD];   // sigmoid(x@W_t + b_t)

// ---------------------------------------------------------------------------
// K1: one warp per adjacency row, float4 loads (LDG.128).
// Computes degree, norm = rsqrt(deg+1e-6), compacts nonzeros into a
// fixed-capacity CSR. Order within the row is lane-major (not strictly
// column-sorted) — SpMM reduction is order-independent.
// Reads adj exactly once (256 MB) -> HBM-bound.
// ---------------------------------------------------------------------------
__global__ void k_deg_csr(const float* __restrict__ adj) {
    int w    = (blockIdx.x * blockDim.x + threadIdx.x) >> 5;
    int lane = threadIdx.x & 31;
    if (w >= MM) return;
    const float4* rowp = (const float4*)(adj + (size_t)w * NN);
    int  base_out = w * MAXNZ;
    int  bbase    = w & ~(NN - 1);   // batch offset for global source row id
    float degacc = 0.f;
    int   cnt    = 0;
    #pragma unroll 2
    for (int it = 0; it < NN / 128; ++it) {       // 32 iterations
        float4 v = rowp[it * 32 + lane];
        degacc += fabsf(v.x) + fabsf(v.y) + fabsf(v.z) + fabsf(v.w);
        int lc = (v.x != 0.f) + (v.y != 0.f) + (v.z != 0.f) + (v.w != 0.f);
        // warp inclusive scan of lc
        int scan = lc;
        #pragma unroll
        for (int o = 1; o < 32; o <<= 1) {
            int t = __shfl_up_sync(0xffffffffu, scan, o);
            if (lane >= o) scan += t;
        }
        int pos = cnt + (scan - lc);
        int col = bbase + it * 128 + lane * 4;
        if (v.x != 0.f && pos < MAXNZ) { g_cidx[base_out + pos] = col + 0; g_cval[base_out + pos] = v.x; pos++; }
        if (v.y != 0.f && pos < MAXNZ) { g_cidx[base_out + pos] = col + 1; g_cval[base_out + pos] = v.y; pos++; }
        if (v.z != 0.f && pos < MAXNZ) { g_cidx[base_out + pos] = col + 2; g_cval[base_out + pos] = v.z; pos++; }
        if (v.w != 0.f && pos < MAXNZ) { g_cidx[base_out + pos] = col + 3; g_cval[base_out + pos] = v.w; pos++; }
        cnt += __shfl_sync(0xffffffffu, scan, 31);
    }
    #pragma unroll
    for (int o = 16; o; o >>= 1)
        degacc += __shfl_xor_sync(0xffffffffu, degacc, o);
    if (lane == 0) {
        g_nnz[w]  = cnt < MAXNZ ? cnt : MAXNZ;
        g_norm[w] = rsqrtf(degacc + 1e-6f);
    }
}

// ---------------------------------------------------------------------------
// K2: fused fp32 GEMM  x[16384,256] @ {theta, W_h, W_t}[256,256]
// 64x64 block tile, 256 threads, 4x4 micro-tile, BK=16.
// blockIdx.y in [0,12): y/4 selects the weight matrix + epilogue,
// y%4 selects the 64-col tile.
// ---------------------------------------------------------------------------
__global__ __launch_bounds__(256) void k_gemm(
    const float* __restrict__ x,
    const float* __restrict__ theta,
    const float* __restrict__ Wh,
    const float* __restrict__ Wt,
    const float* __restrict__ bt)
{
    __shared__ float As[16][64];   // [k][m]
    __shared__ float Bs[16][64];   // [k][n]

    int mat = blockIdx.y >> 2;
    const float* Bmat = (mat == 0) ? theta : (mat == 1) ? Wh : Wt;
    int n0  = (blockIdx.y & 3) * 64;
    int m0  = blockIdx.x * 64;
    int tid = threadIdx.x;
    int tx  = tid & 15;       // n micro
    int ty  = tid >> 4;       // m micro

    float acc[4][4] = {};

    int la_m = tid >> 2;            // 0..63
    int la_k = (tid & 3) * 4;       // 0,4,8,12
    int lb_k = tid >> 4;            // 0..15
    int lb_n = (tid & 15) * 4;      // 0..60

    for (int k0 = 0; k0 < DD; k0 += 16) {
        float4 av = *(const float4*)(x + (size_t)(m0 + la_m) * DD + k0 + la_k);
        As[la_k + 0][la_m] = av.x;
        As[la_k + 1][la_m] = av.y;
        As[la_k + 2][la_m] = av.z;
        As[la_k + 3][la_m] = av.w;
        float4 bv = *(const float4*)(Bmat + (size_t)(k0 + lb_k) * DD + n0 + lb_n);
        *(float4*)&Bs[lb_k][lb_n] = bv;
        __syncthreads();
        #pragma unroll
        for (int kk = 0; kk < 16; ++kk) {
            float a[4], b[4];
            #pragma unroll
            for (int i = 0; i < 4; ++i) a[i] = As[kk][ty * 4 + i];
            #pragma unroll
            for (int j = 0; j < 4; ++j) b[j] = Bs[kk][tx * 4 + j];
            #pragma unroll
            for (int i = 0; i < 4; ++i)
                #pragma unroll
                for (int j = 0; j < 4; ++j)
                    acc[i][j] += a[i] * b[j];
        }
        __syncthreads();
    }

    #pragma unroll
    for (int i = 0; i < 4; ++i) {
        int r = m0 + ty * 4 + i;
        float nrm = g_norm[r];
        #pragma unroll
        for (int j = 0; j < 4; ++j) {
            int c = n0 + tx * 4 + j;
            float v = acc[i][j];
            size_t o = (size_t)r * DD + c;
            if (mat == 0) {
                g_h[o] = v * nrm;
            } else if (mat == 1) {
                g_het[o] = v;
            } else {
                float z = v + bt[c];
                g_gate[o] = 1.f / (1.f + expf(-z));
            }
        }
    }
}

// ---------------------------------------------------------------------------
// K3: per-row sparse gather + gate/combine + ELU.
// One block (256 threads = one channel each) per output row.
// h table (16 MB) is L2-resident -> L2-bound gather.
// ---------------------------------------------------------------------------
__global__ __launch_bounds__(256) void k_spmm(float* __restrict__ out) {
    int row = blockIdx.x;
    int d   = threadIdx.x;
    __shared__ int   sidx[MAXNZ];
    __shared__ float sval[MAXNZ];
    int nnz = g_nnz[row];
    if (d < nnz) {
        sidx[d] = g_cidx[row * MAXNZ + d];
        sval[d] = g_cval[row * MAXNZ + d];
    }
    __syncthreads();
    float acc = 0.f;
    for (int e = 0; e < nnz; ++e)
        acc += sval[e] * g_h[(size_t)sidx[e] * DD + d];
    size_t o  = (size_t)row * DD + d;
    float hom = acc * g_norm[row];
    float g   = g_gate[o];
    float het = g_het[o];
    float f   = g * hom + (1.f - g) * het;
    out[o] = f > 0.f ? f : expm1f(f);
}

// ---------------------------------------------------------------------------
extern "C" void kernel_launch(void* const* d_in, const int* in_sizes, int n_in,
                              void* d_out, int out_size) {
    const float* x     = (const float*)d_in[0];
    const float* adj   = (const float*)d_in[1];
    const float* theta = (const float*)d_in[2];
    const float* Wh    = (const float*)d_in[3];
    const float* Wt    = (const float*)d_in[4];
    const float* bt    = (const float*)d_in[5];
    float* out = (float*)d_out;

    // K1: 16384 warps, 8 warps/block
    k_deg_csr<<<MM / 8, 256>>>(adj);
    // K2: M/64 x (3 matrices * 256/64)
    dim3 g2(MM / 64, 12);
    k_gemm<<<g2, 256>>>(x, theta, Wh, Wt, bt);
    // K3: one block per row
    k_spmm<<<MM, 256>>>(out);
}

// round 4
// speedup vs baseline: 1.4433x; 1.4433x over previous
#include <cuda_runtime.h>
#include <cuda_bf16.h>
#include <math.h>
#include <stdint.h>

// Problem constants
#define BB    4
#define NN    4096
#define DD    256
#define MM    (BB * NN)        // 16384 flattened rows
#define MAXNZ 128              // Poisson(32) row nnz; P(>128) ~ 0

// ---------------------------------------------------------------------------
// Scratch (static __device__ — no allocations allowed)
// ---------------------------------------------------------------------------
static __device__ float          g_norm[MM];
static __device__ int            g_nnz[MM];
static __device__ int            g_cidx[MM * MAXNZ];
static __device__ float          g_cval[MM * MAXNZ];
static __device__ float          g_h[MM * DD];      // norm-scaled x@theta
static __device__ float          g_het[MM * DD];    // x@W_h
static __device__ float          g_gate[MM * DD];   // sigmoid(x@W_t + b_t)
static __device__ __nv_bfloat16  g_xhi[MM * DD];
static __device__ __nv_bfloat16  g_xlo[MM * DD];
// W^T splits: [mat][hi/lo][n][k], each DD*DD
static __device__ __nv_bfloat16  g_wt[3 * 2 * DD * DD];

// ---------------------------------------------------------------------------
// PTX helpers (sm_100 plain target: mma.sync / ldmatrix / cp.async only)
// ---------------------------------------------------------------------------
__device__ __forceinline__ uint32_t smem_u32(const void* p) {
    uint32_t a;
    asm("{ .reg .u64 t; cvta.to.shared.u64 t, %1; cvt.u32.u64 %0, t; }" : "=r"(a) : "l"(p));
    return a;
}
__device__ __forceinline__ void cp16(uint32_t dst, const void* src) {
    asm volatile("cp.async.cg.shared.global [%0], [%1], 16;" :: "r"(dst), "l"(src));
}
#define CP_COMMIT() asm volatile("cp.async.commit_group;" ::: "memory")
#define CP_WAIT(n)  asm volatile("cp.async.wait_group %0;" :: "n"(n) : "memory")

__device__ __forceinline__ void ldsm4(uint32_t* r, uint32_t a) {
    asm volatile("ldmatrix.sync.aligned.m8n8.x4.shared.b16 {%0,%1,%2,%3}, [%4];"
        : "=r"(r[0]), "=r"(r[1]), "=r"(r[2]), "=r"(r[3]) : "r"(a));
}
__device__ __forceinline__ void mma16816(float* d, const uint32_t* a, const uint32_t* b) {
    asm volatile(
        "mma.sync.aligned.m16n8k16.row.col.f32.bf16.bf16.f32 "
        "{%0,%1,%2,%3}, {%4,%5,%6,%7}, {%8,%9}, {%0,%1,%2,%3};"
        : "+f"(d[0]), "+f"(d[1]), "+f"(d[2]), "+f"(d[3])
        : "r"(a[0]), "r"(a[1]), "r"(a[2]), "r"(a[3]), "r"(b[0]), "r"(b[1]));
}

// ---------------------------------------------------------------------------
// K0a: split x into bf16 hi/lo
// ---------------------------------------------------------------------------
__global__ __launch_bounds__(256) void k_split_x(const float* __restrict__ x) {
    int i = blockIdx.x * blockDim.x + threadIdx.x;   // over MM*DD/4
    float4 v = ((const float4*)x)[i];
    __nv_bfloat16 hx = __float2bfloat16(v.x), hy = __float2bfloat16(v.y);
    __nv_bfloat16 hz = __float2bfloat16(v.z), hw = __float2bfloat16(v.w);
    __nv_bfloat16 lx = __float2bfloat16(v.x - __bfloat162float(hx));
    __nv_bfloat16 ly = __float2bfloat16(v.y - __bfloat162float(hy));
    __nv_bfloat16 lz = __float2bfloat16(v.z - __bfloat162float(hz));
    __nv_bfloat16 lw = __float2bfloat16(v.w - __bfloat162float(hw));
    __nv_bfloat162* ph = (__nv_bfloat162*)&g_xhi[i * 4];
    __nv_bfloat162* pl = (__nv_bfloat162*)&g_xlo[i * 4];
    ph[0] = __nv_bfloat162(hx, hy); ph[1] = __nv_bfloat162(hz, hw);
    pl[0] = __nv_bfloat162(lx, ly); pl[1] = __nv_bfloat162(lz, lw);
}

// ---------------------------------------------------------------------------
// K0b: build W^T hi/lo for the 3 weight matrices
// ---------------------------------------------------------------------------
__global__ __launch_bounds__(256) void k_prep_w(const float* __restrict__ theta,
                                                const float* __restrict__ Wh,
                                                const float* __restrict__ Wt) {
    int i = blockIdx.x * blockDim.x + threadIdx.x;   // over 3*DD*DD
    int mat = i >> 16;
    int r   = i & 65535;
    int n   = r >> 8;
    int k   = r & 255;
    const float* W = (mat == 0) ? theta : (mat == 1) ? Wh : Wt;
    float v = W[k * DD + n];
    __nv_bfloat16 hi = __float2bfloat16(v);
    __nv_bfloat16 lo = __float2bfloat16(v - __bfloat162float(hi));
    g_wt[((size_t)(mat * 2 + 0) << 16) + n * DD + k] = hi;
    g_wt[((size_t)(mat * 2 + 1) << 16) + n * DD + k] = lo;
}

// ---------------------------------------------------------------------------
// K1: one warp per adjacency row, float4 loads. HBM-bound (52us, 65% DRAM).
// ---------------------------------------------------------------------------
__global__ void k_deg_csr(const float* __restrict__ adj) {
    int w    = (blockIdx.x * blockDim.x + threadIdx.x) >> 5;
    int lane = threadIdx.x & 31;
    if (w >= MM) return;
    const float4* rowp = (const float4*)(adj + (size_t)w * NN);
    int  base_out = w * MAXNZ;
    int  bbase    = w & ~(NN - 1);
    float degacc = 0.f;
    int   cnt    = 0;
    #pragma unroll 2
    for (int it = 0; it < NN / 128; ++it) {
        float4 v = rowp[it * 32 + lane];
        degacc += fabsf(v.x) + fabsf(v.y) + fabsf(v.z) + fabsf(v.w);
        int lc = (v.x != 0.f) + (v.y != 0.f) + (v.z != 0.f) + (v.w != 0.f);
        int scan = lc;
        #pragma unroll
        for (int o = 1; o < 32; o <<= 1) {
            int t = __shfl_up_sync(0xffffffffu, scan, o);
            if (lane >= o) scan += t;
        }
        int pos = cnt + (scan - lc);
        int col = bbase + it * 128 + lane * 4;
        if (v.x != 0.f && pos < MAXNZ) { g_cidx[base_out + pos] = col + 0; g_cval[base_out + pos] = v.x; pos++; }
        if (v.y != 0.f && pos < MAXNZ) { g_cidx[base_out + pos] = col + 1; g_cval[base_out + pos] = v.y; pos++; }
        if (v.z != 0.f && pos < MAXNZ) { g_cidx[base_out + pos] = col + 2; g_cval[base_out + pos] = v.z; pos++; }
        if (v.w != 0.f && pos < MAXNZ) { g_cidx[base_out + pos] = col + 3; g_cval[base_out + pos] = v.w; pos++; }
        cnt += __shfl_sync(0xffffffffu, scan, 31);
    }
    #pragma unroll
    for (int o = 16; o; o >>= 1)
        degacc += __shfl_xor_sync(0xffffffffu, degacc, o);
    if (lane == 0) {
        g_nnz[w]  = cnt < MAXNZ ? cnt : MAXNZ;
        g_norm[w] = rsqrtf(degacc + 1e-6f);
    }
}

// ---------------------------------------------------------------------------
// K2: bf16-split GEMM via mma.sync.m16n8k16 (tensor pipe on plain sm_100).
// CTA tile 128x128 (8 warps: 4m x 2n, warp tile 32x64). BK=32, cp.async
// double-buffered. 24 K-iterations = 3 split segments x (256/32).
// smem rows padded to 80B -> conflict-free ldmatrix (r*80 mod 128 distinct
// for 8 consecutive rows).
// ---------------------------------------------------------------------------
#define ROWB     80
#define TILE_B   (128 * ROWB)        // 10240 bytes per tile
#define STAGE_B  (2 * TILE_B)        // A + B

__global__ __launch_bounds__(256, 2) void k_gemm_mma(const float* __restrict__ bt) {
    __shared__ __align__(128) char sm[2 * STAGE_B];  // 40960 bytes

    const int tid  = threadIdx.x;
    const int wid  = tid >> 5;
    const int lane = tid & 31;
    const int wm   = wid & 3;      // m warp (32 rows each)
    const int wn   = wid >> 2;     // n warp (64 cols each)
    const int g    = lane >> 3;    // ldmatrix address group
    const int lr   = lane & 7;

    const int mat   = blockIdx.y >> 1;
    const int nhalf = blockIdx.y & 1;
    const int m0    = blockIdx.x * 128;
    const int n0    = nhalf * 128;
    const __nv_bfloat16* wt_hi = g_wt + ((size_t)(mat * 2) << 16);
    const __nv_bfloat16* wt_lo = wt_hi + (1 << 16);

    const uint32_t smb = smem_u32(sm);

    float acc[2][8][4] = {};

    // cp.async of one stage: A tile rows=m, B tile rows=n, 32 bf16 (64B) per row
    auto load_stage = [&](int iter, int stage) {
        const int seg = iter >> 3;              // 24 iters -> 3 segs of 8
        const int k0  = (iter & 7) * 32;
        const __nv_bfloat16* Asrc = (seg < 2) ? g_xhi : g_xlo;
        const __nv_bfloat16* Bsrc = (seg == 1) ? wt_lo : wt_hi;
        const uint32_t sa = smb + stage * STAGE_B;
        const uint32_t sb = sa + TILE_B;
        #pragma unroll
        for (int j = 0; j < 2; ++j) {
            int id  = tid + j * 256;            // 0..511
            int row = id >> 2, c = id & 3;
            cp16(sa + row * ROWB + c * 16, Asrc + (size_t)(m0 + row) * DD + k0 + c * 8);
            cp16(sb + row * ROWB + c * 16, Bsrc + (size_t)(n0 + row) * DD + k0 + c * 8);
        }
    };

    load_stage(0, 0);
    CP_COMMIT();

    // precompute per-thread ldmatrix row offsets
    int arow[2], brow[4];
    #pragma unroll
    for (int mi = 0; mi < 2; ++mi) arow[mi] = (wm * 32 + mi * 16 + (g & 1) * 8 + lr) * ROWB;
    #pragma unroll
    for (int nt = 0; nt < 4; ++nt) brow[nt] = (wn * 64 + nt * 16 + (g >> 1) * 8 + lr) * ROWB;
    const int akb = (g >> 1) * 16;   // A: k-half from address group
    const int bkb = (g & 1) * 16;    // B: k-half from address group

    for (int it = 0; it < 24; ++it) {
        if (it + 1 < 24) { load_stage(it + 1, (it + 1) & 1); CP_COMMIT(); CP_WAIT(1); }
        else             { CP_WAIT(0); }
        __syncthreads();

        const uint32_t sa = smb + (it & 1) * STAGE_B;
        const uint32_t sb = sa + TILE_B;

        #pragma unroll
        for (int ks = 0; ks < 2; ++ks) {
            uint32_t afrag[2][4], bfrag[4][4];
            #pragma unroll
            for (int mi = 0; mi < 2; ++mi)
                ldsm4(afrag[mi], sa + arow[mi] + ks * 32 + akb);
            #pragma unroll
            for (int nt = 0; nt < 4; ++nt)
                ldsm4(bfrag[nt], sb + brow[nt] + ks * 32 + bkb);
            #pragma unroll
            for (int mi = 0; mi < 2; ++mi)
                #pragma unroll
                for (int ni = 0; ni < 8; ++ni)
                    mma16816(acc[mi][ni], afrag[mi], &bfrag[ni >> 1][(ni & 1) * 2]);
        }
        __syncthreads();
    }

    // Epilogue: D fragment (row = lane/4 (+8), cols = (lane%4)*2 + {0,1})
    float* dst = (mat == 0) ? g_h : (mat == 1) ? g_het : g_gate;
    #pragma unroll
    for (int mi = 0; mi < 2; ++mi) {
        #pragma unroll
        for (int rh = 0; rh < 2; ++rh) {
            const int r = m0 + wm * 32 + mi * 16 + rh * 8 + (lane >> 2);
            const float nrm = (mat == 0) ? g_norm[r] : 0.f;
            #pragma unroll
            for (int ni = 0; ni < 8; ++ni) {
                const int c = n0 + wn * 64 + ni * 8 + (lane & 3) * 2;
                float v0 = acc[mi][ni][rh * 2];
                float v1 = acc[mi][ni][rh * 2 + 1];
                if (mat == 0) { v0 *= nrm; v1 *= nrm; }
                else if (mat == 2) {
                    v0 = 1.f / (1.f + expf(-(v0 + bt[c])));
                    v1 = 1.f / (1.f + expf(-(v1 + bt[c + 1])));
                }
                *(float2*)(dst + (size_t)r * DD + c) = make_float2(v0, v1);
            }
        }
    }
}

// ---------------------------------------------------------------------------
// K3: per-row sparse gather + gate/combine + ELU. L2-bound.
// ---------------------------------------------------------------------------
__global__ __launch_bounds__(256) void k_spmm(float* __restrict__ out) {
    int row = blockIdx.x;
    int d   = threadIdx.x;
    __shared__ int   sidx[MAXNZ];
    __shared__ float sval[MAXNZ];
    int nnz = g_nnz[row];
    if (d < nnz) {
        sidx[d] = g_cidx[row * MAXNZ + d];
        sval[d] = g_cval[row * MAXNZ + d];
    }
    __syncthreads();
    float acc = 0.f;
    for (int e = 0; e < nnz; ++e)
        acc += sval[e] * g_h[(size_t)sidx[e] * DD + d];
    size_t o  = (size_t)row * DD + d;
    float hom = acc * g_norm[row];
    float g   = g_gate[o];
    float het = g_het[o];
    float f   = g * hom + (1.f - g) * het;
    out[o] = f > 0.f ? f : expm1f(f);
}

// ---------------------------------------------------------------------------
extern "C" void kernel_launch(void* const* d_in, const int* in_sizes, int n_in,
                              void* d_out, int out_size) {
    const float* x     = (const float*)d_in[0];
    const float* adj   = (const float*)d_in[1];
    const float* theta = (const float*)d_in[2];
    const float* Wh    = (const float*)d_in[3];
    const float* Wt    = (const float*)d_in[4];
    const float* bt    = (const float*)d_in[5];
    float* out = (float*)d_out;

    k_split_x<<<MM * DD / 4 / 256, 256>>>(x);
    k_prep_w<<<3 * DD * DD / 256, 256>>>(theta, Wh, Wt);
    k_deg_csr<<<MM / 8, 256>>>(adj);
    dim3 g2(MM / 128, 6);
    k_gemm_mma<<<g2, 256>>>(bt);
    k_spmm<<<MM, 256>>>(out);
}

// round 5
// speedup vs baseline: 1.5317x; 1.0613x over previous
#include <cuda_runtime.h>
#include <cuda_bf16.h>
#include <math.h>
#include <stdint.h>

// Problem constants
#define BB    4
#define NN    4096
#define DD    256
#define MM    (BB * NN)        // 16384 flattened rows
#define MAXNZ 128              // Binomial(4096, 32/4096): mean 32, 128 = +17 sigma

// ---------------------------------------------------------------------------
// Scratch (static __device__ — no allocations allowed)
// ---------------------------------------------------------------------------
static __device__ float          g_norm[MM];
static __device__ int            g_nnz[MM];
static __device__ int            g_cidx[MM * MAXNZ];
static __device__ float          g_cval[MM * MAXNZ];   // pre-scaled by norm[src]
static __device__ float          g_h[MM * DD];      // raw x@theta (no norm)
static __device__ float          g_het[MM * DD];    // x@W_h
static __device__ float          g_gate[MM * DD];   // sigmoid(x@W_t + b_t)
static __device__ __nv_bfloat16  g_xhi[MM * DD];
static __device__ __nv_bfloat16  g_xlo[MM * DD];
// W^T splits: [mat][hi/lo][n][k], each DD*DD
static __device__ __nv_bfloat16  g_wt[3 * 2 * DD * DD];

// ---------------------------------------------------------------------------
// PTX helpers (plain sm_100 target: mma.sync / ldmatrix / cp.async)
// ---------------------------------------------------------------------------
__device__ __forceinline__ uint32_t smem_u32(const void* p) {
    uint32_t a;
    asm("{ .reg .u64 t; cvta.to.shared.u64 t, %1; cvt.u32.u64 %0, t; }" : "=r"(a) : "l"(p));
    return a;
}
__device__ __forceinline__ void cp16(uint32_t dst, const void* src) {
    asm volatile("cp.async.cg.shared.global [%0], [%1], 16;" :: "r"(dst), "l"(src));
}
#define CP_COMMIT() asm volatile("cp.async.commit_group;" ::: "memory")
#define CP_WAIT(n)  asm volatile("cp.async.wait_group %0;" :: "n"(n) : "memory")

__device__ __forceinline__ void ldsm4(uint32_t* r, uint32_t a) {
    asm volatile("ldmatrix.sync.aligned.m8n8.x4.shared.b16 {%0,%1,%2,%3}, [%4];"
        : "=r"(r[0]), "=r"(r[1]), "=r"(r[2]), "=r"(r[3]) : "r"(a));
}
__device__ __forceinline__ void mma16816(float* d, const uint32_t* a, const uint32_t* b) {
    asm volatile(
        "mma.sync.aligned.m16n8k16.row.col.f32.bf16.bf16.f32 "
        "{%0,%1,%2,%3}, {%4,%5,%6,%7}, {%8,%9}, {%0,%1,%2,%3};"
        : "+f"(d[0]), "+f"(d[1]), "+f"(d[2]), "+f"(d[3])
        : "r"(a[0]), "r"(a[1]), "r"(a[2]), "r"(a[3]), "r"(b[0]), "r"(b[1]));
}

// 64B-row swizzle: off ^ ((off>>3)&0x30); for intra<64 only the row term
// contributes, so s(row) = (row*8)&48.
__device__ __forceinline__ int swz(int row, int intra) {
    return row * 64 + (intra ^ ((row * 8) & 48));
}

// ---------------------------------------------------------------------------
// K0a: split x into bf16 hi/lo
// ---------------------------------------------------------------------------
__global__ __launch_bounds__(256) void k_split_x(const float* __restrict__ x) {
    int i = blockIdx.x * blockDim.x + threadIdx.x;   // over MM*DD/4
    float4 v = ((const float4*)x)[i];
    __nv_bfloat16 hx = __float2bfloat16(v.x), hy = __float2bfloat16(v.y);
    __nv_bfloat16 hz = __float2bfloat16(v.z), hw = __float2bfloat16(v.w);
    __nv_bfloat16 lx = __float2bfloat16(v.x - __bfloat162float(hx));
    __nv_bfloat16 ly = __float2bfloat16(v.y - __bfloat162float(hy));
    __nv_bfloat16 lz = __float2bfloat16(v.z - __bfloat162float(hz));
    __nv_bfloat16 lw = __float2bfloat16(v.w - __bfloat162float(hw));
    __nv_bfloat162* ph = (__nv_bfloat162*)&g_xhi[i * 4];
    __nv_bfloat162* pl = (__nv_bfloat162*)&g_xlo[i * 4];
    ph[0] = __nv_bfloat162(hx, hy); ph[1] = __nv_bfloat162(hz, hw);
    pl[0] = __nv_bfloat162(lx, ly); pl[1] = __nv_bfloat162(lz, lw);
}

// ---------------------------------------------------------------------------
// K0b: build W^T hi/lo for the 3 weight matrices
// ---------------------------------------------------------------------------
__global__ __launch_bounds__(256) void k_prep_w(const float* __restrict__ theta,
                                                const float* __restrict__ Wh,
                                                const float* __restrict__ Wt) {
    int i = blockIdx.x * blockDim.x + threadIdx.x;   // over 3*DD*DD
    int mat = i >> 16;
    int r   = i & 65535;
    int n   = r >> 8;
    int k   = r & 255;
    const float* W = (mat == 0) ? theta : (mat == 1) ? Wh : Wt;
    float v = W[k * DD + n];
    __nv_bfloat16 hi = __float2bfloat16(v);
    __nv_bfloat16 lo = __float2bfloat16(v - __bfloat162float(hi));
    g_wt[((size_t)(mat * 2 + 0) << 16) + n * DD + k] = hi;
    g_wt[((size_t)(mat * 2 + 1) << 16) + n * DD + k] = lo;
}

// ---------------------------------------------------------------------------
// K1: one warp per adjacency row, float4 loads. HBM-bound (52us, 65% DRAM).
// ---------------------------------------------------------------------------
__global__ void k_deg_csr(const float* __restrict__ adj) {
    int w    = (blockIdx.x * blockDim.x + threadIdx.x) >> 5;
    int lane = threadIdx.x & 31;
    if (w >= MM) return;
    const float4* rowp = (const float4*)(adj + (size_t)w * NN);
    int  base_out = w * MAXNZ;
    int  bbase    = w & ~(NN - 1);
    float degacc = 0.f;
    int   cnt    = 0;
    #pragma unroll 2
    for (int it = 0; it < NN / 128; ++it) {
        float4 v = rowp[it * 32 + lane];
        degacc += fabsf(v.x) + fabsf(v.y) + fabsf(v.z) + fabsf(v.w);
        int lc = (v.x != 0.f) + (v.y != 0.f) + (v.z != 0.f) + (v.w != 0.f);
        int scan = lc;
        #pragma unroll
        for (int o = 1; o < 32; o <<= 1) {
            int t = __shfl_up_sync(0xffffffffu, scan, o);
            if (lane >= o) scan += t;
        }
        int pos = cnt + (scan - lc);
        int col = bbase + it * 128 + lane * 4;
        if (v.x != 0.f && pos < MAXNZ) { g_cidx[base_out + pos] = col + 0; g_cval[base_out + pos] = v.x; pos++; }
        if (v.y != 0.f && pos < MAXNZ) { g_cidx[base_out + pos] = col + 1; g_cval[base_out + pos] = v.y; pos++; }
        if (v.z != 0.f && pos < MAXNZ) { g_cidx[base_out + pos] = col + 2; g_cval[base_out + pos] = v.z; pos++; }
        if (v.w != 0.f && pos < MAXNZ) { g_cidx[base_out + pos] = col + 3; g_cval[base_out + pos] = v.w; pos++; }
        cnt += __shfl_sync(0xffffffffu, scan, 31);
    }
    #pragma unroll
    for (int o = 16; o; o >>= 1)
        degacc += __shfl_xor_sync(0xffffffffu, degacc, o);
    if (lane == 0) {
        g_nnz[w]  = cnt < MAXNZ ? cnt : MAXNZ;
        g_norm[w] = rsqrtf(degacc + 1e-6f);
    }
}

// ---------------------------------------------------------------------------
// K1b: fold source-node norm into CSR values: cval[e] *= norm[cidx[e]].
// Removes the GEMM's dependency on K1 (h stays un-normalized).
// ---------------------------------------------------------------------------
__global__ __launch_bounds__(256) void k_scale_cval() {
    int w    = (blockIdx.x * blockDim.x + threadIdx.x) >> 5;
    int lane = threadIdx.x & 31;
    int nnz  = g_nnz[w];
    #pragma unroll
    for (int k = 0; k < MAXNZ / 32; ++k) {
        int e = lane + k * 32;
        if (e < nnz) {
            int o = w * MAXNZ + e;
            g_cval[o] *= g_norm[g_cidx[o]];
        }
    }
}

// ---------------------------------------------------------------------------
// K2: bf16-split GEMM via mma.sync.m16n8k16.
// CTA tile 128x128 (8 warps: 4m x 2n, warp tile 32x64). BK=32.
// 3-stage cp.async ring, ONE __syncthreads per iteration.
// smem: 64B rows + XOR swizzle -> conflict-free ldmatrix; 3x16KB = 48KB.
// 24 K-iterations = 3 split segments (hi*hi, hi*lo, lo*hi) x 8.
// ---------------------------------------------------------------------------
#define TILE_B   (128 * 64)          // 8192 bytes per tile (A or B)
#define STAGE_B  (2 * TILE_B)        // 16384

__global__ __launch_bounds__(256, 2) void k_gemm_mma(const float* __restrict__ bt) {
    __shared__ __align__(128) char sm[3 * STAGE_B];  // 49152 bytes

    const int tid  = threadIdx.x;
    const int wid  = tid >> 5;
    const int lane = tid & 31;
    const int wm   = wid & 3;      // m warp (32 rows each)
    const int wn   = wid >> 2;     // n warp (64 cols each)
    const int g    = lane >> 3;    // ldmatrix address group
    const int lr   = lane & 7;

    const int mat   = blockIdx.y >> 1;
    const int nhalf = blockIdx.y & 1;
    const int m0    = blockIdx.x * 128;
    const int n0    = nhalf * 128;
    const __nv_bfloat16* wt_hi = g_wt + ((size_t)(mat * 2) << 16);
    const __nv_bfloat16* wt_lo = wt_hi + (1 << 16);

    const uint32_t smb = smem_u32(sm);

    float acc[2][8][4] = {};

    // cp.async of one stage (A rows = m, B rows = n, 32 bf16 = 64B per row)
    auto load_stage = [&](int iter, int stage) {
        const int seg = iter >> 3;              // 24 iters -> 3 segs of 8
        const int k0  = (iter & 7) * 32;
        const __nv_bfloat16* Asrc = (seg < 2) ? g_xhi : g_xlo;
        const __nv_bfloat16* Bsrc = (seg == 1) ? wt_lo : wt_hi;
        const uint32_t sa = smb + stage * STAGE_B;
        const uint32_t sb = sa + TILE_B;
        #pragma unroll
        for (int j = 0; j < 2; ++j) {
            int id  = tid + j * 256;            // 0..511
            int row = id >> 2, c = id & 3;
            int so  = swz(row, c * 16);
            cp16(sa + so, Asrc + (size_t)(m0 + row) * DD + k0 + c * 8);
            cp16(sb + so, Bsrc + (size_t)(n0 + row) * DD + k0 + c * 8);
        }
        CP_COMMIT();
    };

    // Per-thread ldmatrix offsets (swizzled), relative to stage base.
    int aoff[2][2], boff[4][2];
    #pragma unroll
    for (int mi = 0; mi < 2; ++mi) {
        int r = wm * 32 + mi * 16 + (g & 1) * 8 + lr;
        #pragma unroll
        for (int ks = 0; ks < 2; ++ks)
            aoff[mi][ks] = swz(r, ks * 32 + (g >> 1) * 16);
    }
    #pragma unroll
    for (int nt = 0; nt < 4; ++nt) {
        int r = wn * 64 + nt * 16 + (g >> 1) * 8 + lr;
        #pragma unroll
        for (int ks = 0; ks < 2; ++ks)
            boff[nt][ks] = swz(r, ks * 32 + (g & 1) * 16);
    }

    load_stage(0, 0);
    load_stage(1, 1);

    int stage = 0;
    for (int it = 0; it < 24; ++it) {
        CP_WAIT(1);          // stage `it` resident (<=1 group pending)
        __syncthreads();     // also protects buffer overwritten by it+2 load

        if (it + 2 < 24) load_stage(it + 2, (stage + 2) % 3);

        const uint32_t sa = smb + stage * STAGE_B;
        const uint32_t sb = sa + TILE_B;

        #pragma unroll
        for (int ks = 0; ks < 2; ++ks) {
            uint32_t afrag[2][4], bfrag[4][4];
            #pragma unroll
            for (int mi = 0; mi < 2; ++mi)
                ldsm4(afrag[mi], sa + aoff[mi][ks]);
            #pragma unroll
            for (int nt = 0; nt < 4; ++nt)
                ldsm4(bfrag[nt], sb + boff[nt][ks]);
            #pragma unroll
            for (int mi = 0; mi < 2; ++mi)
                #pragma unroll
                for (int ni = 0; ni < 8; ++ni)
                    mma16816(acc[mi][ni], afrag[mi], &bfrag[ni >> 1][(ni & 1) * 2]);
        }
        stage = (stage + 1) % 3;
    }

    // Epilogue: D fragment (row = lane/4 (+8), cols = (lane%4)*2 + {0,1})
    float* dst = (mat == 0) ? g_h : (mat == 1) ? g_het : g_gate;
    #pragma unroll
    for (int mi = 0; mi < 2; ++mi) {
        #pragma unroll
        for (int rh = 0; rh < 2; ++rh) {
            const int r = m0 + wm * 32 + mi * 16 + rh * 8 + (lane >> 2);
            #pragma unroll
            for (int ni = 0; ni < 8; ++ni) {
                const int c = n0 + wn * 64 + ni * 8 + (lane & 3) * 2;
                float v0 = acc[mi][ni][rh * 2];
                float v1 = acc[mi][ni][rh * 2 + 1];
                if (mat == 2) {
                    v0 = 1.f / (1.f + expf(-(v0 + bt[c])));
                    v1 = 1.f / (1.f + expf(-(v1 + bt[c + 1])));
                }
                *(float2*)(dst + (size_t)r * DD + c) = make_float2(v0, v1);
            }
        }
    }
}

// ---------------------------------------------------------------------------
// K3: per-row sparse gather + gate/combine + ELU. L2-bound.
// hom_i = norm_i * sum_e cval'_e * h[cidx_e]   (cval' already has norm_src)
// ---------------------------------------------------------------------------
__global__ __launch_bounds__(256) void k_spmm(float* __restrict__ out) {
    int row = blockIdx.x;
    int d   = threadIdx.x;
    __shared__ int   sidx[MAXNZ];
    __shared__ float sval[MAXNZ];
    int nnz = g_nnz[row];
    if (d < nnz) {
        sidx[d] = g_cidx[row * MAXNZ + d];
        sval[d] = g_cval[row * MAXNZ + d];
    }
    __syncthreads();
    float acc = 0.f;
    for (int e = 0; e < nnz; ++e)
        acc += sval[e] * g_h[(size_t)sidx[e] * DD + d];
    size_t o  = (size_t)row * DD + d;
    float hom = acc * g_norm[row];
    float g   = g_gate[o];
    float het = g_het[o];
    float f   = g * hom + (1.f - g) * het;
    out[o] = f > 0.f ? f : expm1f(f);
}

// ---------------------------------------------------------------------------
extern "C" void kernel_launch(void* const* d_in, const int* in_sizes, int n_in,
                              void* d_out, int out_size) {
    const float* x     = (const float*)d_in[0];
    const float* adj   = (const float*)d_in[1];
    const float* theta = (const float*)d_in[2];
    const float* Wh    = (const float*)d_in[3];
    const float* Wt    = (const float*)d_in[4];
    const float* bt    = (const float*)d_in[5];
    float* out = (float*)d_out;

    k_split_x<<<MM * DD / 4 / 256, 256>>>(x);
    k_prep_w<<<3 * DD * DD / 256, 256>>>(theta, Wh, Wt);
    k_deg_csr<<<MM / 8, 256>>>(adj);
    k_scale_cval<<<MM / 8, 256>>>();
    dim3 g2(MM / 128, 6);
    k_gemm_mma<<<g2, 256>>>(bt);
    k_spmm<<<MM, 256>>>(out);
}